// round 6
// baseline (speedup 1.0000x reference)
#include <cuda_runtime.h>
#include <cuda_fp16.h>
#include <cstdint>
#include <math.h>

#define N_TOK 8192
#define DIM   1024

// ----------------------------- scratch -------------------------------------
__device__ __align__(256) __half g_eh[(size_t)N_TOK * DIM];
__device__ __align__(256) int8_t g_e8[(size_t)N_TOK * 2 * DIM];   // [lo|hi]
__device__ __align__(256) __half g_wh[(size_t)3 * DIM * DIM];
__device__ __align__(256) int8_t g_w8[(size_t)3 * 2 * DIM * DIM]; // [hi|lo]
__device__ __align__(256) __half g_qh[(size_t)N_TOK * DIM];
__device__ __align__(256) int8_t g_q8[(size_t)N_TOK * 2 * DIM];   // [lo|hi]
__device__ __align__(256) __half g_kh[(size_t)N_TOK * DIM];
__device__ __align__(256) int8_t g_k8[(size_t)N_TOK * 2 * DIM];   // [hi|lo]
__device__ __align__(256) __half g_vth[(size_t)DIM * N_TOK];      // V^T hi
__device__ __align__(256) float  g_s[(size_t)N_TOK * N_TOK];
__device__ __align__(256) __half g_ph[(size_t)N_TOK * N_TOK];

// ----------------------------- scale constants -----------------------------
// bounds: |E|,|Q|,|K| < 8 -> fp16 lo-limb <= 2^-9 < 2e-3 ; |W| < 0.25 -> lo <= 2^-14 < 6.25e-5
#define F_LO   63500.0f          // 127 / 2e-3     (lo of 8-bounded values)
#define F_HI8  15.875f           // 127 / 8        (hi of 8-bounded values)
#define F_W8   508.0f            // 127 / 0.25
#define F_WL   2032000.0f        // 127 / 6.25e-5
#define SIG_QKV 3.1000062e-8f    // (2e-3/127)*(0.25/127)  == (8/127)*(6.25e-5/127)
#define SIG_S   9.9200198e-7f    // (2e-3/127)*(8/127)

// ----------------------------- helpers -------------------------------------
__device__ __forceinline__ uint32_t smem_u32(const void* p) {
    uint32_t a;
    asm("{ .reg .u64 t; cvta.to.shared.u64 t, %1; cvt.u32.u64 %0, t; }" : "=r"(a) : "l"(p));
    return a;
}
__device__ __forceinline__ void cp16(uint32_t dst, const void* src) {
    asm volatile("cp.async.cg.shared.global [%0], [%1], 16;" :: "r"(dst), "l"(src));
}
__device__ __forceinline__ void cp_commit() { asm volatile("cp.async.commit_group;" ::: "memory"); }
template <int N> __device__ __forceinline__ void cp_wait() {
    asm volatile("cp.async.wait_group %0;" :: "n"(N) : "memory");
}
#define LDSM4(r, addr) \
    asm volatile("ldmatrix.sync.aligned.m8n8.x4.shared.b16 {%0,%1,%2,%3}, [%4];" \
                 : "=r"((r)[0]), "=r"((r)[1]), "=r"((r)[2]), "=r"((r)[3]) : "r"(addr))
#define MMA16816(c, a, b0, b1) \
    asm volatile("mma.sync.aligned.m16n8k16.row.col.f32.f16.f16.f32 " \
                 "{%0,%1,%2,%3},{%4,%5,%6,%7},{%8,%9},{%0,%1,%2,%3};" \
                 : "+f"((c)[0]), "+f"((c)[1]), "+f"((c)[2]), "+f"((c)[3]) \
                 : "r"((a)[0]), "r"((a)[1]), "r"((a)[2]), "r"((a)[3]), "r"(b0), "r"(b1))
#define IMMA16832(c, a, b0, b1) \
    asm volatile("mma.sync.aligned.m16n8k32.row.col.s32.s8.s8.s32 " \
                 "{%0,%1,%2,%3},{%4,%5,%6,%7},{%8,%9},{%0,%1,%2,%3};" \
                 : "+r"((c)[0]), "+r"((c)[1]), "+r"((c)[2]), "+r"((c)[3]) \
                 : "r"((a)[0]), "r"((a)[1]), "r"((a)[2]), "r"((a)[3]), "r"(b0), "r"(b1))

__device__ __forceinline__ int8_t q8(float v, float f) {
    return (int8_t)__float2int_rn(fminf(fmaxf(v * f, -127.0f), 127.0f));
}

// ----------------------------- hybrid GEMM ---------------------------------
// C[M,N] = Ah[M,K]@Bh[N,K]^T (fp16, fp32 acc)
//        + sigma * A8[M,2K]@B8[N,2K]^T (int8, int32 acc)   [if HYB]
// swapA/swapB: read int8 halves rotated by K (role-swapped tensors).
// biasMode: 0 none, 1 per-col, 2 per-row.
// outMode: 0 f32 Cf; 2 fp16 Ch only; 3 fp16 Ch + int8 limbs C8 (loFirstOut conv).
#define KC 32
#define ROWP 80
#define TILEB (128 * ROWP)
#define STAGEB (4 * TILEB)      // Ah, A8, Bh, B8
#define GSMEM (3 * STAGEB)      // 122880 B

template <int HYB>
__global__ __launch_bounds__(256, 1)
void gemm_h(const __half* __restrict__ Ah, const int8_t* __restrict__ A8, int lda,
            const __half* __restrict__ Bh, const int8_t* __restrict__ B8, int ldb,
            const float* __restrict__ bias, int biasMode,
            float* __restrict__ Cf, __half* __restrict__ Ch, int8_t* __restrict__ C8,
            int ldc, int K, int outMode, int swapA, int swapB,
            float sigma, float fClo, float fChi, int loFirstOut)
{
    extern __shared__ char smem[];
    const uint32_t sb = smem_u32(smem);
    const int t = threadIdx.x, lane = t & 31, wid = t >> 5;
    const int wm = wid >> 2, wn = wid & 3;
    const int m0 = blockIdx.y * 128, n0 = blockIdx.x * 128;
    const int S = K / KC;
    const int K2 = 2 * K;

    auto load_stage = [&](int s, int buf) {
        const int kt = s * KC;
        int koA = s * 64 + (swapA ? K : 0); if (koA >= K2) koA -= K2;
        int koB = s * 64 + (swapB ? K : 0); if (koB >= K2) koB -= K2;
        const uint32_t base = sb + (uint32_t)buf * STAGEB;
#pragma unroll
        for (int half = 0; half < 2; half++) {
            const int cid = half * 256 + t;
            const int row = cid >> 2, ch = cid & 3;
            const uint32_t off = row * ROWP + ch * 16;
            cp16(base + 0 * TILEB + off, Ah + (size_t)(m0 + row) * lda + kt + ch * 8);
            cp16(base + 2 * TILEB + off, Bh + (size_t)(n0 + row) * ldb + kt + ch * 8);
            if (HYB) {
                cp16(base + 1 * TILEB + off, A8 + (size_t)(m0 + row) * K2 + koA + ch * 16);
                cp16(base + 3 * TILEB + off, B8 + (size_t)(n0 + row) * K2 + koB + ch * 16);
            }
        }
        cp_commit();
    };

    float cf[4][4][4];
    int   ci[4][4][4];
#pragma unroll
    for (int i = 0; i < 4; i++)
#pragma unroll
        for (int j = 0; j < 4; j++)
#pragma unroll
            for (int q = 0; q < 4; q++) { cf[i][j][q] = 0.0f; if (HYB) ci[i][j][q] = 0; }

    load_stage(0, 0);
    load_stage(1, 1);
    load_stage(2, 2);

    const uint32_t arow = (uint32_t)(wm * 64 + (lane & 15));
    const uint32_t brow = (uint32_t)(wn * 32 + (lane & 15));
    const uint32_t kby = (uint32_t)((lane >> 4) * 16);
    // int8 ldmatrix lane mapping: rows interleaved 8-blocks, 16B col halves
    const uint32_t i8r = (uint32_t)((lane & 7) + ((lane >> 3) & 1) * 8);
    const uint32_t i8c = (uint32_t)((lane >> 4) * 16);

    for (int s = 0; s < S; s++) {
        if (s < S - 2) cp_wait<2>(); else if (s == S - 2) cp_wait<1>(); else cp_wait<0>();
        __syncthreads();
        const uint32_t base = sb + (uint32_t)(s % 3) * STAGEB;

#pragma unroll
        for (int kh = 0; kh < 2; kh++) {
            const uint32_t ko = kh * 32 + kby;
            {
                uint32_t ah[4][4], bh[2][4];
#pragma unroll
                for (int mi = 0; mi < 4; mi++)
                    LDSM4(ah[mi], base + (arow + mi * 16) * ROWP + ko);
#pragma unroll
                for (int g = 0; g < 2; g++)
                    LDSM4(bh[g], base + 2 * TILEB + (brow + g * 16) * ROWP + ko);
#pragma unroll
                for (int mi = 0; mi < 4; mi++)
#pragma unroll
                    for (int ni = 0; ni < 4; ni++)
                        MMA16816(cf[mi][ni], ah[mi], bh[ni >> 1][ni & 1], bh[ni >> 1][(ni & 1) + 2]);
            }
            if (HYB) {
                const uint32_t ko8 = kh * 32 + i8c;
                uint32_t a8[4][4], b8[2][4];
#pragma unroll
                for (int mi = 0; mi < 4; mi++)
                    LDSM4(a8[mi], base + 1 * TILEB + (wm * 64 + mi * 16 + i8r) * ROWP + ko8);
#pragma unroll
                for (int g = 0; g < 2; g++)
                    LDSM4(b8[g], base + 3 * TILEB + (wn * 32 + g * 16 + i8r) * ROWP + ko8);
#pragma unroll
                for (int mi = 0; mi < 4; mi++)
#pragma unroll
                    for (int ni = 0; ni < 4; ni++)
                        IMMA16832(ci[mi][ni], a8[mi], b8[ni >> 1][ni & 1], b8[ni >> 1][(ni & 1) + 2]);
            }
        }
        __syncthreads();
        if (s + 3 < S) load_stage(s + 3, s % 3);
    }

    // ----------------------------- epilogue --------------------------------
    const int rbase = m0 + wm * 64 + (lane >> 2);
    const int cbase = n0 + wn * 32 + (lane & 3) * 2;
#pragma unroll
    for (int mi = 0; mi < 4; mi++) {
#pragma unroll
        for (int ni = 0; ni < 4; ni++) {
            const int col = cbase + ni * 8;
            float bc0 = 0.0f, bc1 = 0.0f;
            if (biasMode == 1) { bc0 = bias[col]; bc1 = bias[col + 1]; }
#pragma unroll
            for (int h = 0; h < 2; h++) {
                const int row = rbase + mi * 16 + h * 8;
                float v0 = cf[mi][ni][2 * h + 0] + bc0;
                float v1 = cf[mi][ni][2 * h + 1] + bc1;
                if (HYB) {
                    v0 += sigma * (float)ci[mi][ni][2 * h + 0];
                    v1 += sigma * (float)ci[mi][ni][2 * h + 1];
                }
                if (biasMode == 2) { const float br = bias[row]; v0 += br; v1 += br; }
                const size_t off = (size_t)row * ldc + col;
                if (outMode == 0) {
                    *(float2*)(Cf + off) = make_float2(v0, v1);
                } else {
                    const __half h0 = __float2half(v0), h1 = __float2half(v1);
                    __half2 hp = __halves2half2(h0, h1);
                    *(uint32_t*)(Ch + off) = *(uint32_t*)&hp;
                    if (outMode == 3) {
                        const float l0 = v0 - __half2float(h0);
                        const float l1 = v1 - __half2float(h1);
                        int8_t lo0 = q8(l0, fClo), lo1 = q8(l1, fClo);
                        int8_t hi0 = q8(v0, fChi), hi1 = q8(v1, fChi);
                        const size_t b8off = (size_t)row * (2 * ldc);
                        const int loOff = loFirstOut ? 0 : ldc;
                        const int hiOff = loFirstOut ? ldc : 0;
                        short lp = (short)((uint8_t)lo0 | ((uint16_t)(uint8_t)lo1 << 8));
                        short hp2 = (short)((uint8_t)hi0 | ((uint16_t)(uint8_t)hi1 << 8));
                        *(short*)(C8 + b8off + loOff + col) = lp;
                        *(short*)(C8 + b8off + hiOff + col) = hp2;
                    }
                }
            }
        }
    }
}

// ----------------------------- prep: fp32 -> fp16 hi + int8 limb pair ------
__global__ __launch_bounds__(256)
void prep8(const float* __restrict__ x, __half* __restrict__ xh,
           int8_t* __restrict__ x8, int K, float fLo, float fHi, int loFirst)
{
    const int i4 = blockIdx.x * 256 + threadIdx.x;
    const int flat = i4 * 4;
    const int row = flat / K, col = flat - row * K;
    float4 v = ((const float4*)x)[i4];
    __half h0 = __float2half(v.x), h1 = __float2half(v.y);
    __half h2 = __float2half(v.z), h3 = __float2half(v.w);
    __half2 a = __halves2half2(h0, h1), b = __halves2half2(h2, h3);
    ((uint2*)xh)[i4] = make_uint2(*(uint32_t*)&a, *(uint32_t*)&b);
    char4 lo, hi;
    lo.x = q8(v.x - __half2float(h0), fLo);
    lo.y = q8(v.y - __half2float(h1), fLo);
    lo.z = q8(v.z - __half2float(h2), fLo);
    lo.w = q8(v.w - __half2float(h3), fLo);
    hi.x = q8(v.x, fHi); hi.y = q8(v.y, fHi);
    hi.z = q8(v.z, fHi); hi.w = q8(v.w, fHi);
    const size_t base = (size_t)row * 2 * K;
    *(char4*)(x8 + base + (loFirst ? col : K + col)) = lo;
    *(char4*)(x8 + base + (loFirst ? K + col : col)) = hi;
}

// ----------------------------- softmax (fp16 hi out) -----------------------
__global__ __launch_bounds__(256)
void softmax_hi(const float* __restrict__ S, __half* __restrict__ Ph)
{
    const size_t row = blockIdx.x;
    const float* p = S + row * N_TOK;
    const int t = threadIdx.x, lane = t & 31, warp = t >> 5;
    __shared__ float red[10];

    float4 v[8];
    float mx = -INFINITY;
#pragma unroll
    for (int i = 0; i < 8; i++) {
        v[i] = *(const float4*)(p + (size_t)(i * 256 + t) * 4);
        mx = fmaxf(mx, fmaxf(fmaxf(v[i].x, v[i].y), fmaxf(v[i].z, v[i].w)));
    }
#pragma unroll
    for (int o = 16; o > 0; o >>= 1) mx = fmaxf(mx, __shfl_xor_sync(~0u, mx, o));
    if (lane == 0) red[warp] = mx;
    __syncthreads();
    if (t == 0) { float m = red[0]; for (int w = 1; w < 8; w++) m = fmaxf(m, red[w]); red[8] = m; }
    __syncthreads();
    mx = red[8];

    float sum = 0.0f;
#pragma unroll
    for (int i = 0; i < 8; i++) {
        v[i].x = __expf(v[i].x - mx); v[i].y = __expf(v[i].y - mx);
        v[i].z = __expf(v[i].z - mx); v[i].w = __expf(v[i].w - mx);
        sum += (v[i].x + v[i].y) + (v[i].z + v[i].w);
    }
#pragma unroll
    for (int o = 16; o > 0; o >>= 1) sum += __shfl_xor_sync(~0u, sum, o);
    if (lane == 0) red[warp] = sum;
    __syncthreads();
    if (t == 0) { float s = 0.0f; for (int w = 0; w < 8; w++) s += red[w]; red[9] = s; }
    __syncthreads();
    const float inv = 1.0f / red[9];

#pragma unroll
    for (int i = 0; i < 8; i++) {
        __half2 hA = __halves2half2(__float2half(v[i].x * inv), __float2half(v[i].y * inv));
        __half2 hB = __halves2half2(__float2half(v[i].z * inv), __float2half(v[i].w * inv));
        const size_t idx = row * (N_TOK / 4) + (size_t)(i * 256 + t);
        ((uint2*)Ph)[idx] = make_uint2(*(uint32_t*)&hA, *(uint32_t*)&hB);
    }
}

// ----------------------------- launch --------------------------------------
extern "C" void kernel_launch(void* const* d_in, const int* in_sizes, int n_in,
                              void* d_out, int out_size)
{
    const float* emb = (const float*)d_in[0];
    const float* Wq  = (const float*)d_in[1];
    const float* bq  = (const float*)d_in[2];
    const float* Wk  = (const float*)d_in[3];
    const float* bk  = (const float*)d_in[4];
    const float* Wv  = (const float*)d_in[5];
    const float* bv  = (const float*)d_in[6];
    float* out = (float*)d_out;

    __half *eh, *wh, *qh, *kh, *vth, *ph;
    int8_t *e8, *w8, *q8p, *k8p;
    float* s;
    cudaGetSymbolAddress((void**)&eh, g_eh);   cudaGetSymbolAddress((void**)&e8, g_e8);
    cudaGetSymbolAddress((void**)&wh, g_wh);   cudaGetSymbolAddress((void**)&w8, g_w8);
    cudaGetSymbolAddress((void**)&qh, g_qh);   cudaGetSymbolAddress((void**)&q8p, g_q8);
    cudaGetSymbolAddress((void**)&kh, g_kh);   cudaGetSymbolAddress((void**)&k8p, g_k8);
    cudaGetSymbolAddress((void**)&vth, g_vth);
    cudaGetSymbolAddress((void**)&s, g_s);
    cudaGetSymbolAddress((void**)&ph, g_ph);

    static int once = 0;
    if (!once) {
        cudaFuncSetAttribute(gemm_h<1>, cudaFuncAttributeMaxDynamicSharedMemorySize, GSMEM);
        cudaFuncSetAttribute(gemm_h<0>, cudaFuncAttributeMaxDynamicSharedMemorySize, GSMEM);
        once = 1;
    }

    const size_t WSZ = (size_t)DIM * DIM;       // fp16 weight matrix stride
    const size_t W8SZ = 2 * WSZ;                // int8 limb-pair stride

    // preps: E (A-conv: lo first), W (B-conv: hi first)
    prep8<<<N_TOK * DIM / 4 / 256, 256>>>(emb, eh, e8, DIM, F_LO, F_HI8, 1);
    prep8<<<DIM * DIM / 4 / 256, 256>>>(Wq, wh, w8, DIM, F_WL, F_W8, 0);
    prep8<<<DIM * DIM / 4 / 256, 256>>>(Wk, wh + WSZ, w8 + W8SZ, DIM, F_WL, F_W8, 0);
    prep8<<<DIM * DIM / 4 / 256, 256>>>(Wv, wh + 2 * WSZ, w8 + 2 * W8SZ, DIM, F_WL, F_W8, 0);

    // Q = E@Wq^T + bq -> fp16 + limbs (A-conv for scores)
    gemm_h<1><<<dim3(DIM / 128, N_TOK / 128), 256, GSMEM>>>(
        eh, e8, DIM, wh, w8, DIM, bq, 1,
        nullptr, qh, q8p, DIM, DIM, 3, 0, 0, SIG_QKV, F_LO, F_HI8, 1);
    // K = E@Wk^T + bk -> fp16 + limbs (B-conv for scores)
    gemm_h<1><<<dim3(DIM / 128, N_TOK / 128), 256, GSMEM>>>(
        eh, e8, DIM, wh + WSZ, w8 + W8SZ, DIM, bk, 1,
        nullptr, kh, k8p, DIM, DIM, 3, 0, 0, SIG_QKV, F_LO, F_HI8, 0);
    // V^T = Wv@E^T + bv(row) -> fp16 hi only (swapped int8 halves both sides)
    gemm_h<1><<<dim3(N_TOK / 128, DIM / 128), 256, GSMEM>>>(
        wh + 2 * WSZ, w8 + 2 * W8SZ, DIM, eh, e8, DIM, bv, 2,
        nullptr, vth, nullptr, N_TOK, DIM, 2, 1, 1, SIG_QKV, 0.0f, 0.0f, 0);
    // S = Q@K^T -> fp32
    gemm_h<1><<<dim3(N_TOK / 128, N_TOK / 128), 256, GSMEM>>>(
        qh, q8p, DIM, kh, k8p, DIM, nullptr, 0,
        s, nullptr, nullptr, N_TOK, DIM, 0, 0, 0, SIG_S, 0.0f, 0.0f, 0);
    // softmax -> fp16
    softmax_hi<<<N_TOK, 256>>>(s, ph);
    // out = P@V (fp16 1-pass)
    gemm_h<0><<<dim3(DIM / 128, N_TOK / 128), 256, GSMEM>>>(
        ph, nullptr, N_TOK, vth, nullptr, N_TOK, nullptr, 0,
        out, nullptr, nullptr, DIM, N_TOK, 0, 0, 0, 0.0f, 0.0f, 0.0f, 0);
}

// round 7
// speedup vs baseline: 1.8774x; 1.8774x over previous
#include <cuda_runtime.h>
#include <cuda_fp16.h>
#include <cstdint>
#include <math.h>

#define N_TOK 8192
#define DIM   1024

// ----------------------------- scratch -------------------------------------
__device__ __align__(256) __half g_eh[(size_t)N_TOK * DIM];
__device__ __align__(256) __half g_el[(size_t)N_TOK * DIM];
__device__ __align__(256) __half g_wh[(size_t)3 * DIM * DIM];
__device__ __align__(256) __half g_wl[(size_t)3 * DIM * DIM];
__device__ __align__(256) __half g_qh[(size_t)N_TOK * DIM];
__device__ __align__(256) __half g_ql[(size_t)N_TOK * DIM];
__device__ __align__(256) __half g_kh[(size_t)N_TOK * DIM];
__device__ __align__(256) __half g_kl[(size_t)N_TOK * DIM];
__device__ __align__(256) __half g_vth[(size_t)DIM * N_TOK];  // V^T hi [D][N]
__device__ __align__(256) float  g_s[(size_t)N_TOK * N_TOK];
__device__ __align__(256) __half g_ph[(size_t)N_TOK * N_TOK];

// ----------------------------- helpers -------------------------------------
__device__ __forceinline__ uint32_t smem_u32(const void* p) {
    uint32_t a;
    asm("{ .reg .u64 t; cvta.to.shared.u64 t, %1; cvt.u32.u64 %0, t; }" : "=r"(a) : "l"(p));
    return a;
}
__device__ __forceinline__ void cp16(uint32_t dst, const void* src) {
    asm volatile("cp.async.cg.shared.global [%0], [%1], 16;" :: "r"(dst), "l"(src));
}
__device__ __forceinline__ void cp_commit() { asm volatile("cp.async.commit_group;" ::: "memory"); }
template <int N> __device__ __forceinline__ void cp_wait() {
    asm volatile("cp.async.wait_group %0;" :: "n"(N) : "memory");
}
#define LDSM4(r, addr) \
    asm volatile("ldmatrix.sync.aligned.m8n8.x4.shared.b16 {%0,%1,%2,%3}, [%4];" \
                 : "=r"((r)[0]), "=r"((r)[1]), "=r"((r)[2]), "=r"((r)[3]) : "r"(addr))
#define MMA16816(c, a, b0, b1) \
    asm volatile("mma.sync.aligned.m16n8k16.row.col.f32.f16.f16.f32 " \
                 "{%0,%1,%2,%3},{%4,%5,%6,%7},{%8,%9},{%0,%1,%2,%3};" \
                 : "+f"((c)[0]), "+f"((c)[1]), "+f"((c)[2]), "+f"((c)[3]) \
                 : "r"((a)[0]), "r"((a)[1]), "r"((a)[2]), "r"((a)[3]), "r"(b0), "r"(b1))

// ----------------------------- wide split GEMM ------------------------------
// C[M,N] = A[M,K]@B[N,K]^T (+bias); A/B are fp16 hi(+lo) limb pairs.
// NPASS 3: Ah*Bh + Ah*Bl + Al*Bh.  NPASS 1: Ah*Bh.
// CTA tile 128x256, kc=32, 2-stage cp.async, 8 warps (2m x 4n), warp 64x64.
// biasMode: 0 none, 1 per-col, 2 per-row. outMode: 0 f32, 1 fp16 hi+lo, 2 fp16 hi.
#define KC 32
#define ROWP 80
#define A_H 0
#define A_L (128 * ROWP)
#define B_H (2 * 128 * ROWP)
#define B_L (B_H + 256 * ROWP)
#define STAGE (B_L + 256 * ROWP)       // 61440 B
#define GSMEM (2 * STAGE)              // 122880 B

template <int NPASS>
__global__ __launch_bounds__(256, 1)
void gemm_w(const __half* __restrict__ Ah, const __half* __restrict__ Al, int lda,
            const __half* __restrict__ Bh, const __half* __restrict__ Bl, int ldb,
            const float* __restrict__ bias, int biasMode,
            float* __restrict__ Cf, __half* __restrict__ Ch, __half* __restrict__ Cl,
            int ldc, int K, int outMode)
{
    extern __shared__ char smem[];
    const uint32_t sb = smem_u32(smem);
    const int t = threadIdx.x, lane = t & 31, wid = t >> 5;
    const int wm = wid >> 2, wn = wid & 3;        // 2 x 4 warps, warp tile 64x64
    const int m0 = blockIdx.y * 128, n0 = blockIdx.x * 256;
    const int S = K / KC;

    auto load_stage = [&](int s, int buf) {
        const int kt = s * KC;
        const uint32_t base = sb + (uint32_t)buf * STAGE;
#pragma unroll
        for (int i = 0; i < 2; i++) {             // A: 128 rows x 64B
            const int cid = i * 256 + t;
            const int row = cid >> 2, ch = cid & 3;
            const uint32_t off = row * ROWP + ch * 16;
            const size_t g = (size_t)(m0 + row) * lda + kt + ch * 8;
            cp16(base + A_H + off, Ah + g);
            if (NPASS == 3) cp16(base + A_L + off, Al + g);
        }
#pragma unroll
        for (int i = 0; i < 4; i++) {             // B: 256 rows x 64B
            const int cid = i * 256 + t;
            const int row = cid >> 2, ch = cid & 3;
            const uint32_t off = row * ROWP + ch * 16;
            const size_t g = (size_t)(n0 + row) * ldb + kt + ch * 8;
            cp16(base + B_H + off, Bh + g);
            if (NPASS == 3) cp16(base + B_L + off, Bl + g);
        }
        cp_commit();
    };

    float c[4][8][4];
#pragma unroll
    for (int i = 0; i < 4; i++)
#pragma unroll
        for (int j = 0; j < 8; j++)
#pragma unroll
            for (int q = 0; q < 4; q++) c[i][j][q] = 0.0f;

    load_stage(0, 0);
    load_stage(1, 1);

    const uint32_t aoff = (uint32_t)(wm * 64 + (lane & 15)) * ROWP + (uint32_t)((lane >> 4) * 16);
    const uint32_t boff = (uint32_t)(wn * 64 + (lane & 15)) * ROWP + (uint32_t)((lane >> 4) * 16);

    for (int s = 0; s < S; s++) {
        if (s < S - 1) cp_wait<1>(); else cp_wait<0>();
        __syncthreads();
        const uint32_t base = sb + (uint32_t)(s & 1) * STAGE;

#pragma unroll
        for (int kh = 0; kh < 2; kh++) {
            const uint32_t kb = (uint32_t)(kh * 32);
            uint32_t ah[4][4], bx[4][4];
#pragma unroll
            for (int mi = 0; mi < 4; mi++)
                LDSM4(ah[mi], base + A_H + aoff + (uint32_t)(mi * 16 * ROWP) + kb);
#pragma unroll
            for (int g = 0; g < 4; g++)
                LDSM4(bx[g], base + B_H + boff + (uint32_t)(g * 16 * ROWP) + kb);
            // pass hh
#pragma unroll
            for (int mi = 0; mi < 4; mi++)
#pragma unroll
                for (int g = 0; g < 4; g++) {
                    MMA16816(c[mi][2 * g],     ah[mi], bx[g][0], bx[g][2]);
                    MMA16816(c[mi][2 * g + 1], ah[mi], bx[g][1], bx[g][3]);
                }
            if (NPASS == 3) {
                {   // pass hl: Ah x Bl (reuse ah)
                    uint32_t bl[4][4];
#pragma unroll
                    for (int g = 0; g < 4; g++)
                        LDSM4(bl[g], base + B_L + boff + (uint32_t)(g * 16 * ROWP) + kb);
#pragma unroll
                    for (int mi = 0; mi < 4; mi++)
#pragma unroll
                        for (int g = 0; g < 4; g++) {
                            MMA16816(c[mi][2 * g],     ah[mi], bl[g][0], bl[g][2]);
                            MMA16816(c[mi][2 * g + 1], ah[mi], bl[g][1], bl[g][3]);
                        }
                }
                {   // pass lh: Al x Bh (reuse bx)
                    uint32_t al[4][4];
#pragma unroll
                    for (int mi = 0; mi < 4; mi++)
                        LDSM4(al[mi], base + A_L + aoff + (uint32_t)(mi * 16 * ROWP) + kb);
#pragma unroll
                    for (int mi = 0; mi < 4; mi++)
#pragma unroll
                        for (int g = 0; g < 4; g++) {
                            MMA16816(c[mi][2 * g],     al[mi], bx[g][0], bx[g][2]);
                            MMA16816(c[mi][2 * g + 1], al[mi], bx[g][1], bx[g][3]);
                        }
                }
            }
        }
        __syncthreads();
        if (s + 2 < S) load_stage(s + 2, s & 1);
    }

    // ----------------------------- epilogue --------------------------------
    const int rbase = m0 + wm * 64 + (lane >> 2);
    const int cbase = n0 + wn * 64 + (lane & 3) * 2;
#pragma unroll
    for (int mi = 0; mi < 4; mi++) {
#pragma unroll
        for (int nj = 0; nj < 8; nj++) {
            const int col = cbase + nj * 8;
            float bc0 = 0.0f, bc1 = 0.0f;
            if (biasMode == 1) { bc0 = bias[col]; bc1 = bias[col + 1]; }
#pragma unroll
            for (int h = 0; h < 2; h++) {
                const int row = rbase + mi * 16 + h * 8;
                float v0 = c[mi][nj][2 * h + 0] + bc0;
                float v1 = c[mi][nj][2 * h + 1] + bc1;
                if (biasMode == 2) { const float br = bias[row]; v0 += br; v1 += br; }
                const size_t off = (size_t)row * ldc + col;
                if (outMode == 0) {
                    *(float2*)(Cf + off) = make_float2(v0, v1);
                } else {
                    const __half h0 = __float2half(v0), h1 = __float2half(v1);
                    __half2 hp = __halves2half2(h0, h1);
                    *(uint32_t*)(Ch + off) = *(uint32_t*)&hp;
                    if (outMode == 1) {
                        const __half l0 = __float2half(v0 - __half2float(h0));
                        const __half l1 = __float2half(v1 - __half2float(h1));
                        __half2 lp = __halves2half2(l0, l1);
                        *(uint32_t*)(Cl + off) = *(uint32_t*)&lp;
                    }
                }
            }
        }
    }
}

// ----------------------------- elementwise split ---------------------------
__global__ __launch_bounds__(256)
void split_f32(const float* __restrict__ x, __half* __restrict__ h,
               __half* __restrict__ l, int n4)
{
    int i = blockIdx.x * 256 + threadIdx.x;
    if (i >= n4) return;
    float4 v = ((const float4*)x)[i];
    __half h0 = __float2half(v.x), h1 = __float2half(v.y);
    __half h2 = __float2half(v.z), h3 = __float2half(v.w);
    __half2 a = __halves2half2(h0, h1), b = __halves2half2(h2, h3);
    __half2 cc = __halves2half2(__float2half(v.x - __half2float(h0)), __float2half(v.y - __half2float(h1)));
    __half2 d = __halves2half2(__float2half(v.z - __half2float(h2)), __float2half(v.w - __half2float(h3)));
    ((uint2*)h)[i] = make_uint2(*(uint32_t*)&a, *(uint32_t*)&b);
    ((uint2*)l)[i] = make_uint2(*(uint32_t*)&cc, *(uint32_t*)&d);
}

// ----------------------------- softmax (fp16 hi out) -----------------------
__global__ __launch_bounds__(256)
void softmax_hi(const float* __restrict__ S, __half* __restrict__ Ph)
{
    const size_t row = blockIdx.x;
    const float* p = S + row * N_TOK;
    const int t = threadIdx.x, lane = t & 31, warp = t >> 5;
    __shared__ float red[10];

    float4 v[8];
    float mx = -INFINITY;
#pragma unroll
    for (int i = 0; i < 8; i++) {
        v[i] = *(const float4*)(p + (size_t)(i * 256 + t) * 4);
        mx = fmaxf(mx, fmaxf(fmaxf(v[i].x, v[i].y), fmaxf(v[i].z, v[i].w)));
    }
#pragma unroll
    for (int o = 16; o > 0; o >>= 1) mx = fmaxf(mx, __shfl_xor_sync(~0u, mx, o));
    if (lane == 0) red[warp] = mx;
    __syncthreads();
    if (t == 0) { float m = red[0]; for (int w = 1; w < 8; w++) m = fmaxf(m, red[w]); red[8] = m; }
    __syncthreads();
    mx = red[8];

    float sum = 0.0f;
#pragma unroll
    for (int i = 0; i < 8; i++) {
        v[i].x = __expf(v[i].x - mx); v[i].y = __expf(v[i].y - mx);
        v[i].z = __expf(v[i].z - mx); v[i].w = __expf(v[i].w - mx);
        sum += (v[i].x + v[i].y) + (v[i].z + v[i].w);
    }
#pragma unroll
    for (int o = 16; o > 0; o >>= 1) sum += __shfl_xor_sync(~0u, sum, o);
    if (lane == 0) red[warp] = sum;
    __syncthreads();
    if (t == 0) { float s = 0.0f; for (int w = 0; w < 8; w++) s += red[w]; red[9] = s; }
    __syncthreads();
    const float inv = 1.0f / red[9];

#pragma unroll
    for (int i = 0; i < 8; i++) {
        __half2 hA = __halves2half2(__float2half(v[i].x * inv), __float2half(v[i].y * inv));
        __half2 hB = __halves2half2(__float2half(v[i].z * inv), __float2half(v[i].w * inv));
        const size_t idx = row * (N_TOK / 4) + (size_t)(i * 256 + t);
        ((uint2*)Ph)[idx] = make_uint2(*(uint32_t*)&hA, *(uint32_t*)&hB);
    }
}

// ----------------------------- launch --------------------------------------
extern "C" void kernel_launch(void* const* d_in, const int* in_sizes, int n_in,
                              void* d_out, int out_size)
{
    const float* emb = (const float*)d_in[0];
    const float* Wq  = (const float*)d_in[1];
    const float* bq  = (const float*)d_in[2];
    const float* Wk  = (const float*)d_in[3];
    const float* bk  = (const float*)d_in[4];
    const float* Wv  = (const float*)d_in[5];
    const float* bv  = (const float*)d_in[6];
    float* out = (float*)d_out;

    __half *eh, *el, *wh, *wl, *qh, *ql, *kh, *kl, *vth, *ph;
    float* s;
    cudaGetSymbolAddress((void**)&eh, g_eh);   cudaGetSymbolAddress((void**)&el, g_el);
    cudaGetSymbolAddress((void**)&wh, g_wh);   cudaGetSymbolAddress((void**)&wl, g_wl);
    cudaGetSymbolAddress((void**)&qh, g_qh);   cudaGetSymbolAddress((void**)&ql, g_ql);
    cudaGetSymbolAddress((void**)&kh, g_kh);   cudaGetSymbolAddress((void**)&kl, g_kl);
    cudaGetSymbolAddress((void**)&vth, g_vth);
    cudaGetSymbolAddress((void**)&s, g_s);
    cudaGetSymbolAddress((void**)&ph, g_ph);

    static int once = 0;
    if (!once) {
        cudaFuncSetAttribute(gemm_w<3>, cudaFuncAttributeMaxDynamicSharedMemorySize, GSMEM);
        cudaFuncSetAttribute(gemm_w<1>, cudaFuncAttributeMaxDynamicSharedMemorySize, GSMEM);
        once = 1;
    }

    const size_t WSZ = (size_t)DIM * DIM;

    split_f32<<<N_TOK * DIM / 4 / 256, 256>>>(emb, eh, el, N_TOK * DIM / 4);
    split_f32<<<DIM * DIM / 4 / 256, 256>>>(Wq, wh, wl, DIM * DIM / 4);
    split_f32<<<DIM * DIM / 4 / 256, 256>>>(Wk, wh + WSZ, wl + WSZ, DIM * DIM / 4);
    split_f32<<<DIM * DIM / 4 / 256, 256>>>(Wv, wh + 2 * WSZ, wl + 2 * WSZ, DIM * DIM / 4);

    // Q = E @ Wq^T + bq -> fp16 hi/lo   [8192,1024]
    gemm_w<3><<<dim3(DIM / 256, N_TOK / 128), 256, GSMEM>>>(
        eh, el, DIM, wh, wl, DIM, bq, 1, nullptr, qh, ql, DIM, DIM, 1);
    // K = E @ Wk^T + bk -> fp16 hi/lo
    gemm_w<3><<<dim3(DIM / 256, N_TOK / 128), 256, GSMEM>>>(
        eh, el, DIM, wh + WSZ, wl + WSZ, DIM, bk, 1, nullptr, kh, kl, DIM, DIM, 1);
    // V^T = Wv @ E^T + bv(row) -> fp16 hi   [1024,8192]
    gemm_w<3><<<dim3(N_TOK / 256, DIM / 128), 256, GSMEM>>>(
        wh + 2 * WSZ, wl + 2 * WSZ, DIM, eh, el, DIM, bv, 2, nullptr, vth, nullptr, N_TOK, DIM, 2);
    // S = Q @ K^T -> fp32   [8192,8192]
    gemm_w<3><<<dim3(N_TOK / 256, N_TOK / 128), 256, GSMEM>>>(
        qh, ql, DIM, kh, kl, DIM, nullptr, 0, s, nullptr, nullptr, N_TOK, DIM, 0);
    // P = softmax(S) -> fp16 hi
    softmax_hi<<<N_TOK, 256>>>(s, ph);
    // out = P @ (V^T)^T -> fp32   [8192,1024]
    gemm_w<1><<<dim3(DIM / 256, N_TOK / 128), 256, GSMEM>>>(
        ph, nullptr, N_TOK, vth, nullptr, N_TOK, nullptr, 0, out, nullptr, nullptr, DIM, N_TOK, 0);
}